// round 8
// baseline (speedup 1.0000x reference)
#include <cuda_runtime.h>
#include <cstdint>

#define N_NODES   100000
#define N_EDGES   640000
#define IN_FEAT   128

#define SCORE_SCALE     2048.0f      // 2^11 fixed point
#define SCORE_INV_SCALE (1.0f / 2048.0f)

// Edge kernel geometry: one wave, 1 block/SM (224KB smem), all 148 SMs.
#define STAGE_N       57344                      // staged nodes (224KB smem)
#define SMEM_BYTES    (STAGE_N * 4)
#define EDGE_BLOCKS   148
#define EDGE_THREADS  1024
#define EDGE_STRIDE   (EDGE_BLOCKS * EDGE_THREADS)   // 151552
#define EPT           5                               // 151552*5 = 757760 >= 640000

// Packed per-node scores: low int16 = src score, high int16 = trg score.
__device__ int g_score[N_NODES];

// ---------------------------------------------------------------------------
// Kernel 1 (R7): per-node dual dot products, split-warp reduction.
// ---------------------------------------------------------------------------
__global__ __launch_bounds__(512) void node_scores_kernel(
    const float* __restrict__ x,     // [N_NODES, 128]
    const float* __restrict__ W)     // [1, 256] = [W_src(128) | W_trg(128)]
{
    const int warp_in_block = threadIdx.x >> 5;
    const int lane          = threadIdx.x & 31;
    const int half          = lane >> 4;
    const int sub           = lane & 15;

    const int w    = blockIdx.x * 16 + warp_in_block;
    const int node = 2 * w + half;
    if (2 * w >= N_NODES) return;

    const float4* xr = reinterpret_cast<const float4*>(x + (size_t)node * IN_FEAT);
    const float4* w4 = reinterpret_cast<const float4*>(W);

    const float4 x0  = __ldg(xr + sub);
    const float4 x1  = __ldg(xr + sub + 16);
    const float4 ws0 = __ldg(w4 + sub);
    const float4 ws1 = __ldg(w4 + sub + 16);
    const float4 wt0 = __ldg(w4 + 32 + sub);
    const float4 wt1 = __ldg(w4 + 32 + sub + 16);

    float ss = x0.x * ws0.x + x0.y * ws0.y + x0.z * ws0.z + x0.w * ws0.w
             + x1.x * ws1.x + x1.y * ws1.y + x1.z * ws1.z + x1.w * ws1.w;
    float st = x0.x * wt0.x + x0.y * wt0.y + x0.z * wt0.z + x0.w * wt0.w
             + x1.x * wt1.x + x1.y * wt1.y + x1.z * wt1.z + x1.w * wt1.w;

    #pragma unroll
    for (int off = 8; off > 0; off >>= 1) {
        ss += __shfl_xor_sync(0xFFFFFFFFu, ss, off);
        st += __shfl_xor_sync(0xFFFFFFFFu, st, off);
    }

    if (sub == 0) {
        int si = __float2int_rn(fminf(fmaxf(ss * SCORE_SCALE, -32767.0f), 32767.0f));
        int ti = __float2int_rn(fminf(fmaxf(st * SCORE_SCALE, -32767.0f), 32767.0f));
        g_score[node] = (si & 0xFFFF) | (ti << 16);
    }
}

// ---------------------------------------------------------------------------
// Kernel 2: hybrid smem/LDG gather.
// Stage packed scores for nodes [0, STAGE_N) in 224KB smem (57% of table);
// gathers for staged nodes use the smem crossbar (no L1tex replay cost),
// the rest stay LDG. One populate phase, fully unrolled (MLP=14), 1 wave
// over all 148 SMs.
// ---------------------------------------------------------------------------
__global__ __launch_bounds__(EDGE_THREADS) void edge_sigmoid_hybrid_kernel(
    const int*   __restrict__ edge_src,
    const int*   __restrict__ edge_trg,
    const float* __restrict__ b,
    float*       __restrict__ out)
{
    extern __shared__ int sh[];   // STAGE_N packed scores

    // Populate: 14336 int4 per block = 14 per thread, fully unrolled.
    {
        const int4* src = reinterpret_cast<const int4*>(g_score);
        int4*       dst = reinterpret_cast<int4*>(sh);
        #pragma unroll
        for (int k = 0; k < STAGE_N / 4 / EDGE_THREADS; ++k)
            dst[threadIdx.x + k * EDGE_THREADS] =
                __ldg(src + threadIdx.x + k * EDGE_THREADS);
    }

    // Load this thread's edge indices while populate is in flight.
    const int tid = blockIdx.x * EDGE_THREADS + threadIdx.x;
    int s[EPT], t[EPT];
    #pragma unroll
    for (int i = 0; i < EPT; ++i) {
        const int e = tid + i * EDGE_STRIDE;
        const bool v = (e < N_EDGES);
        s[i] = v ? __ldg(edge_src + e) : 0;
        t[i] = v ? __ldg(edge_trg + e) : 0;
    }
    const float bias = __ldg(b);

    __syncthreads();

    // Gather: smem for staged nodes, LDG otherwise. Issue all before use.
    int ps[EPT], pt[EPT];
    #pragma unroll
    for (int i = 0; i < EPT; ++i)
        ps[i] = (s[i] < STAGE_N) ? sh[s[i]] : g_score[s[i]];
    #pragma unroll
    for (int i = 0; i < EPT; ++i)
        pt[i] = (t[i] < STAGE_N) ? sh[t[i]] : g_score[t[i]];

    #pragma unroll
    for (int i = 0; i < EPT; ++i) {
        const int e = tid + i * EDGE_STRIDE;
        if (e < N_EDGES) {
            const float z = (float)((short)(ps[i] & 0xFFFF) + (pt[i] >> 16))
                            * SCORE_INV_SCALE + bias;
            out[e] = 1.0f / (1.0f + __expf(-z));
        }
    }
}

// ---------------------------------------------------------------------------
extern "C" void kernel_launch(void* const* d_in, const int* in_sizes, int n_in,
                              void* d_out, int out_size)
{
    // Identify inputs defensively by element count.
    const float* x  = nullptr;
    const int*   es = nullptr;
    const int*   et = nullptr;
    const float* W  = nullptr;
    const float* b  = nullptr;

    for (int i = 0; i < n_in; ++i) {
        const int n = in_sizes[i];
        if (n == N_NODES * IN_FEAT)      x = (const float*)d_in[i];
        else if (n == N_EDGES) {
            if (!es) es = (const int*)d_in[i];
            else     et = (const int*)d_in[i];
        }
        else if (n == 2 * IN_FEAT)       W = (const float*)d_in[i];
        else if (n == 1)                 b = (const float*)d_in[i];
    }

    float* out = (float*)d_out;

    // Allow 224KB dynamic smem (idempotent host attr, not a device alloc).
    cudaFuncSetAttribute(edge_sigmoid_hybrid_kernel,
                         cudaFuncAttributeMaxDynamicSharedMemorySize,
                         SMEM_BYTES);

    // Kernel 1: 16 warps/block, 2 nodes/warp -> 32 nodes/block
    const int blocks1 = (N_NODES + 31) / 32;
    node_scores_kernel<<<blocks1, 512>>>(x, W);

    // Kernel 2: hybrid gather, one wave across all SMs.
    edge_sigmoid_hybrid_kernel<<<EDGE_BLOCKS, EDGE_THREADS, SMEM_BYTES>>>(es, et, b, out);
}

// round 9
// speedup vs baseline: 1.1050x; 1.1050x over previous
#include <cuda_runtime.h>
#include <cstdint>

#define N_NODES   100000
#define N_EDGES   640000
#define IN_FEAT   128

#define SCORE_SCALE     2048.0f      // 2^11 fixed point
#define SCORE_INV_SCALE (1.0f / 2048.0f)

// Packed per-node scores: low int16 = src score, high int16 = trg score.
__device__ int g_score[N_NODES];

// ---------------------------------------------------------------------------
// Kernel 1 (primary): per-node dual dot products, split-warp reduction.
// Signals PDL dependents immediately after its g_score store.
// ---------------------------------------------------------------------------
__global__ __launch_bounds__(512) void node_scores_kernel(
    const float* __restrict__ x,     // [N_NODES, 128]
    const float* __restrict__ W)     // [1, 256] = [W_src(128) | W_trg(128)]
{
    const int warp_in_block = threadIdx.x >> 5;
    const int lane          = threadIdx.x & 31;
    const int half          = lane >> 4;
    const int sub           = lane & 15;

    const int w    = blockIdx.x * 16 + warp_in_block;
    const int node = 2 * w + half;

    if (2 * w < N_NODES) {
        const float4* xr = reinterpret_cast<const float4*>(x + (size_t)node * IN_FEAT);
        const float4* w4 = reinterpret_cast<const float4*>(W);

        const float4 x0  = __ldg(xr + sub);
        const float4 x1  = __ldg(xr + sub + 16);
        const float4 ws0 = __ldg(w4 + sub);
        const float4 ws1 = __ldg(w4 + sub + 16);
        const float4 wt0 = __ldg(w4 + 32 + sub);
        const float4 wt1 = __ldg(w4 + 32 + sub + 16);

        float ss = x0.x * ws0.x + x0.y * ws0.y + x0.z * ws0.z + x0.w * ws0.w
                 + x1.x * ws1.x + x1.y * ws1.y + x1.z * ws1.z + x1.w * ws1.w;
        float st = x0.x * wt0.x + x0.y * wt0.y + x0.z * wt0.z + x0.w * wt0.w
                 + x1.x * wt1.x + x1.y * wt1.y + x1.z * wt1.z + x1.w * wt1.w;

        #pragma unroll
        for (int off = 8; off > 0; off >>= 1) {
            ss += __shfl_xor_sync(0xFFFFFFFFu, ss, off);
            st += __shfl_xor_sync(0xFFFFFFFFu, st, off);
        }

        if (sub == 0) {
            int si = __float2int_rn(fminf(fmaxf(ss * SCORE_SCALE, -32767.0f), 32767.0f));
            int ti = __float2int_rn(fminf(fmaxf(st * SCORE_SCALE, -32767.0f), 32767.0f));
            g_score[node] = (si & 0xFFFF) | (ti << 16);
        }
    }

    // Allow the dependent (edge) grid to launch; our store above precedes this.
    asm volatile("griddepcontrol.launch_dependents;" ::: "memory");
}

// ---------------------------------------------------------------------------
// Kernel 2 (dependent): per-edge gather + sigmoid, 4 edges per thread.
// Launched with ProgrammaticStreamSerialization: starts during the node
// kernel, loads its (g_score-independent) indices, then waits on the grid
// dependency before gathering.
// ---------------------------------------------------------------------------
__global__ __launch_bounds__(256) void edge_sigmoid_kernel(
    const int*   __restrict__ edge_src,
    const int*   __restrict__ edge_trg,
    const float* __restrict__ b,
    float*       __restrict__ out)
{
    const int g = blockIdx.x * blockDim.x + threadIdx.x;   // group of 4 edges
    if (g * 4 >= N_EDGES) {
        asm volatile("griddepcontrol.wait;" ::: "memory");
        return;
    }

    // Prologue: everything independent of g_score (overlaps primary kernel).
    const float bias = __ldg(b);
    const int4 s4 = __ldg(reinterpret_cast<const int4*>(edge_src) + g);
    const int4 t4 = __ldg(reinterpret_cast<const int4*>(edge_trg) + g);

    // Wait for the node-score kernel's stores to be visible.
    asm volatile("griddepcontrol.wait;" ::: "memory");

    // Issue all 8 gathers before consuming.
    const int ps0 = g_score[s4.x], ps1 = g_score[s4.y];
    const int ps2 = g_score[s4.z], ps3 = g_score[s4.w];
    const int pt0 = g_score[t4.x], pt1 = g_score[t4.y];
    const int pt2 = g_score[t4.z], pt3 = g_score[t4.w];

    float4 r;
    {
        float z;
        z = (float)((short)ps0 + (pt0 >> 16)) * SCORE_INV_SCALE + bias;
        r.x = 1.0f / (1.0f + __expf(-z));
        z = (float)((short)ps1 + (pt1 >> 16)) * SCORE_INV_SCALE + bias;
        r.y = 1.0f / (1.0f + __expf(-z));
        z = (float)((short)ps2 + (pt2 >> 16)) * SCORE_INV_SCALE + bias;
        r.z = 1.0f / (1.0f + __expf(-z));
        z = (float)((short)ps3 + (pt3 >> 16)) * SCORE_INV_SCALE + bias;
        r.w = 1.0f / (1.0f + __expf(-z));
    }
    reinterpret_cast<float4*>(out)[g] = r;
}

// ---------------------------------------------------------------------------
extern "C" void kernel_launch(void* const* d_in, const int* in_sizes, int n_in,
                              void* d_out, int out_size)
{
    // Identify inputs defensively by element count.
    const float* x  = nullptr;
    const int*   es = nullptr;
    const int*   et = nullptr;
    const float* W  = nullptr;
    const float* b  = nullptr;

    for (int i = 0; i < n_in; ++i) {
        const int n = in_sizes[i];
        if (n == N_NODES * IN_FEAT)      x = (const float*)d_in[i];
        else if (n == N_EDGES) {
            if (!es) es = (const int*)d_in[i];
            else     et = (const int*)d_in[i];
        }
        else if (n == 2 * IN_FEAT)       W = (const float*)d_in[i];
        else if (n == 1)                 b = (const float*)d_in[i];
    }

    float* out = (float*)d_out;

    // Kernel 1: 16 warps/block, 2 nodes/warp -> 32 nodes/block
    const int blocks1 = (N_NODES + 31) / 32;
    node_scores_kernel<<<blocks1, 512>>>(x, W);

    // Kernel 2: PDL-launched so its prologue overlaps kernel 1.
    const int threads2 = N_EDGES / 4;                 // divides exactly
    const int blocks2  = (threads2 + 255) / 256;

    cudaLaunchConfig_t cfg = {};
    cfg.gridDim  = dim3((unsigned)blocks2, 1, 1);
    cfg.blockDim = dim3(256, 1, 1);
    cfg.dynamicSmemBytes = 0;
    cfg.stream = 0;  // legacy default stream (same as <<<>>>; captured by harness)

    cudaLaunchAttribute attrs[1];
    attrs[0].id = cudaLaunchAttributeProgrammaticStreamSerialization;
    attrs[0].val.programmaticStreamSerializationAllowed = 1;
    cfg.attrs    = attrs;
    cfg.numAttrs = 1;

    cudaLaunchKernelEx(&cfg, edge_sigmoid_kernel, es, et, b, out);
}

// round 10
// speedup vs baseline: 1.1218x; 1.0152x over previous
#include <cuda_runtime.h>
#include <cstdint>

#define N_NODES   100000
#define N_EDGES   640000
#define IN_FEAT   128

#define SCORE_SCALE     2048.0f      // 2^11 fixed point
#define SCORE_INV_SCALE (1.0f / 2048.0f)

// Edge kernel geometry: one wave, 1 block/SM (224KB smem), all 148 SMs.
#define STAGE_N       57344                      // staged nodes -> 224KB
#define TABLE_BYTES   (STAGE_N * 4)              // 229376
#define MBAR_OFF      TABLE_BYTES                // 16B-aligned
#define SMEM_TOTAL    (TABLE_BYTES + 16)
#define TMA_CHUNK     16384                      // 14 chunks of 16KB
#define N_CHUNKS      (TABLE_BYTES / TMA_CHUNK)

#define EDGE_BLOCKS   148
#define EDGE_THREADS  1024
#define EDGE_STRIDE   (EDGE_BLOCKS * EDGE_THREADS)   // 151552
#define EPT           5                               // 151552*5 >= 640000

// Packed per-node scores: low int16 = src score, high int16 = trg score.
__device__ int g_score[N_NODES];

// ---------------------------------------------------------------------------
// Kernel 1 (R7 winner): per-node dual dot products, split-warp reduction.
// ---------------------------------------------------------------------------
__global__ __launch_bounds__(512) void node_scores_kernel(
    const float* __restrict__ x,     // [N_NODES, 128]
    const float* __restrict__ W)     // [1, 256] = [W_src(128) | W_trg(128)]
{
    const int warp_in_block = threadIdx.x >> 5;
    const int lane          = threadIdx.x & 31;
    const int half          = lane >> 4;
    const int sub           = lane & 15;

    const int w    = blockIdx.x * 16 + warp_in_block;
    const int node = 2 * w + half;
    if (2 * w >= N_NODES) return;

    const float4* xr = reinterpret_cast<const float4*>(x + (size_t)node * IN_FEAT);
    const float4* w4 = reinterpret_cast<const float4*>(W);

    const float4 x0  = __ldg(xr + sub);
    const float4 x1  = __ldg(xr + sub + 16);
    const float4 ws0 = __ldg(w4 + sub);
    const float4 ws1 = __ldg(w4 + sub + 16);
    const float4 wt0 = __ldg(w4 + 32 + sub);
    const float4 wt1 = __ldg(w4 + 32 + sub + 16);

    float ss = x0.x * ws0.x + x0.y * ws0.y + x0.z * ws0.z + x0.w * ws0.w
             + x1.x * ws1.x + x1.y * ws1.y + x1.z * ws1.z + x1.w * ws1.w;
    float st = x0.x * wt0.x + x0.y * wt0.y + x0.z * wt0.z + x0.w * wt0.w
             + x1.x * wt1.x + x1.y * wt1.y + x1.z * wt1.z + x1.w * wt1.w;

    #pragma unroll
    for (int off = 8; off > 0; off >>= 1) {
        ss += __shfl_xor_sync(0xFFFFFFFFu, ss, off);
        st += __shfl_xor_sync(0xFFFFFFFFu, st, off);
    }

    if (sub == 0) {
        int si = __float2int_rn(fminf(fmaxf(ss * SCORE_SCALE, -32767.0f), 32767.0f));
        int ti = __float2int_rn(fminf(fmaxf(st * SCORE_SCALE, -32767.0f), 32767.0f));
        g_score[node] = (si & 0xFFFF) | (ti << 16);
    }
}

// ---------------------------------------------------------------------------
// Kernel 2: hybrid gather with TMA-bulk populate.
// One thread issues 14 cp.async.bulk chunks (L2 -> smem at LTS rate, no LSU);
// meanwhile all threads load their edge indices from DRAM. mbarrier wait,
// then gathers: staged nodes via smem crossbar, the rest via LDG.
// ---------------------------------------------------------------------------
__global__ __launch_bounds__(EDGE_THREADS) void edge_sigmoid_tma_kernel(
    const int*   __restrict__ edge_src,
    const int*   __restrict__ edge_trg,
    const float* __restrict__ b,
    float*       __restrict__ out)
{
    extern __shared__ int sh[];   // [0, STAGE_N): packed scores; then mbarrier
    uint32_t smem_base;
    asm("{ .reg .u64 t; cvta.to.shared.u64 t, %1; cvt.u32.u64 %0, t; }"
        : "=r"(smem_base) : "l"(sh));
    const uint32_t mbar = smem_base + MBAR_OFF;

    // --- init mbarrier, then launch TMA populate from thread 0 ---
    if (threadIdx.x == 0) {
        asm volatile("mbarrier.init.shared.b64 [%0], 1;" :: "r"(mbar) : "memory");
        // make init visible to the async proxy before the bulk ops target it
        asm volatile("fence.proxy.async.shared::cta;" ::: "memory");
        asm volatile("mbarrier.arrive.expect_tx.shared.b64 _, [%0], %1;"
                     :: "r"(mbar), "r"((uint32_t)TABLE_BYTES) : "memory");
        const char* src = reinterpret_cast<const char*>(g_score);
        #pragma unroll
        for (int c = 0; c < N_CHUNKS; ++c) {
            asm volatile(
                "cp.async.bulk.shared::cta.global.mbarrier::complete_tx::bytes "
                "[%0], [%1], %2, [%3];"
                :: "r"(smem_base + c * TMA_CHUNK),
                   "l"(src + c * TMA_CHUNK),
                   "r"((uint32_t)TMA_CHUNK),
                   "r"(mbar)
                : "memory");
        }
    }

    // --- overlapped: coalesced index loads (DRAM path) ---
    const int tid = blockIdx.x * EDGE_THREADS + threadIdx.x;
    int s[EPT], t[EPT];
    #pragma unroll
    for (int i = 0; i < EPT; ++i) {
        const int e = tid + i * EDGE_STRIDE;
        const bool v = (e < N_EDGES);
        s[i] = v ? __ldg(edge_src + e) : 0;
        t[i] = v ? __ldg(edge_trg + e) : 0;
    }
    const float bias = __ldg(b);

    // all threads see the inited barrier via this sync, then wait on TMA
    __syncthreads();
    {
        uint32_t done;
        asm volatile(
            "{\n\t.reg .pred p;\n\t"
            "mbarrier.try_wait.parity.acquire.cta.shared::cta.b64 p, [%1], %2;\n\t"
            "selp.b32 %0, 1, 0, p;\n\t}"
            : "=r"(done) : "r"(mbar), "r"(0u) : "memory");
        if (!done) {
            asm volatile(
                "{\n\t.reg .pred P1;\n\t"
                "WAIT_LOOP:\n\t"
                "mbarrier.try_wait.parity.acquire.cta.shared::cta.b64 P1, [%0], %1, 0x989680;\n\t"
                "@P1 bra.uni WAIT_DONE;\n\t"
                "bra.uni WAIT_LOOP;\n\t"
                "WAIT_DONE:\n\t}"
                :: "r"(mbar), "r"(0u) : "memory");
        }
    }

    // --- gathers: smem for staged nodes, LDG otherwise; issue all first ---
    int ps[EPT], pt[EPT];
    #pragma unroll
    for (int i = 0; i < EPT; ++i)
        ps[i] = (s[i] < STAGE_N) ? sh[s[i]] : g_score[s[i]];
    #pragma unroll
    for (int i = 0; i < EPT; ++i)
        pt[i] = (t[i] < STAGE_N) ? sh[t[i]] : g_score[t[i]];

    #pragma unroll
    for (int i = 0; i < EPT; ++i) {
        const int e = tid + i * EDGE_STRIDE;
        if (e < N_EDGES) {
            const float z = (float)((short)(ps[i] & 0xFFFF) + (pt[i] >> 16))
                            * SCORE_INV_SCALE + bias;
            out[e] = 1.0f / (1.0f + __expf(-z));
        }
    }
}

// ---------------------------------------------------------------------------
extern "C" void kernel_launch(void* const* d_in, const int* in_sizes, int n_in,
                              void* d_out, int out_size)
{
    // Identify inputs defensively by element count.
    const float* x  = nullptr;
    const int*   es = nullptr;
    const int*   et = nullptr;
    const float* W  = nullptr;
    const float* b  = nullptr;

    for (int i = 0; i < n_in; ++i) {
        const int n = in_sizes[i];
        if (n == N_NODES * IN_FEAT)      x = (const float*)d_in[i];
        else if (n == N_EDGES) {
            if (!es) es = (const int*)d_in[i];
            else     et = (const int*)d_in[i];
        }
        else if (n == 2 * IN_FEAT)       W = (const float*)d_in[i];
        else if (n == 1)                 b = (const float*)d_in[i];
    }

    float* out = (float*)d_out;

    // Allow large dynamic smem (idempotent host attr, not a device alloc).
    cudaFuncSetAttribute(edge_sigmoid_tma_kernel,
                         cudaFuncAttributeMaxDynamicSharedMemorySize,
                         SMEM_TOTAL);

    // Kernel 1: 16 warps/block, 2 nodes/warp -> 32 nodes/block
    const int blocks1 = (N_NODES + 31) / 32;
    node_scores_kernel<<<blocks1, 512>>>(x, W);

    // Kernel 2: hybrid gather, one wave across all SMs.
    edge_sigmoid_tma_kernel<<<EDGE_BLOCKS, EDGE_THREADS, SMEM_TOTAL>>>(es, et, b, out);
}